// round 11
// baseline (speedup 1.0000x reference)
#include <cuda_runtime.h>
#include <cuda_bf16.h>
#include <math.h>

// pred[b] = sigmoid(gb + data[b,:].bias + || data[b,:] @ embed ||^2)
//   (the (B,F,F) Gram double-sum collapses to the squared norm of s = x @ V)
//
// Grid = 128 blocks (fg 0..15 x bg 0..7), 512 threads, one wave.
// Block (fg, bg): 8 batch rows x 128 features x all 64 dims.
//   - warp w owns s-quad dq=w; lane bit4 splits the 8-feature slice in two
//     -> 128 FMAs/thread, 4 warps/SMSP to hide LDS/SHFL latency
//   - ALL global loads front-batched (4 embed LDG.128 + bias + x) so L2/DRAM
//     latency overlaps the x STS/BAR drain
//   - 5-round reduce-scatter butterfly: each lane ends with exactly ONE fully
//     reduced value (index == lane) -> single fully-spread REDG.ADD per lane
//   - hierarchical finish: one acq_rel ticket per batch group (8 counters on
//     distinct 128B lines); the 16th block of a group finishes its 8 rows
//     (2KB readback) and resets its slice + counter (replay-deterministic).

#define F_NUM   2048
#define D_DIM   64
#define BATCH   64
#define THREADS 512
#define BGC     8          // batch groups (8 rows each)
#define FGC     16         // feature groups per batch group
#define FPB     128        // features per block
#define BPB     8          // batch rows per block

__device__ float        g_s[BATCH][D_DIM];   // zero-init; re-zeroed by finishers
__device__ float        g_lin[BATCH];
__device__ unsigned int g_counter[BGC * 32]; // one counter per 128B line

__global__ __launch_bounds__(THREADS, 1)
void KTM_22110491640579_kernel(const float* __restrict__ data,
                               const float* __restrict__ embed,
                               const float* __restrict__ bias,
                               const float* __restrict__ gbias,
                               float* __restrict__ out) {
    __shared__ float4 xs4[BPB][FPB / 4];      // 4 KB x tile [8][32 quads]
    __shared__ unsigned int s_ticket;

    const int tid  = threadIdx.x;
    const int fg   = blockIdx.x & (FGC - 1);  // 0..15
    const int bg   = blockIdx.x >> 4;         // 0..7
    const int f0   = fg * FPB;
    const int b0   = bg * BPB;
    const int w    = tid >> 5;                // warp 0..15 == s-quad dq
    const int lane = tid & 31;

    const int fs = lane & 15;                 // 16 slices of 8 features
    const int fh = lane >> 4;                 // which 4-feature half
    // this thread's 4 features: f0 + fs*8 + fh*4 + {0..3}, quad w of embed row
    const float4* V4 = ((const float4*)embed)
                     + ((size_t)(f0 + fs * 8 + fh * 4) * 16 + w);

    // ---- front-batch ALL global loads (independent addresses) ----
    float4 ev[4];
    #pragma unroll
    for (int j = 0; j < 4; ++j) ev[j] = V4[(size_t)j * 16];
    float bv[4];
    if (w < BPB) {                            // bias slice for the linear term
        #pragma unroll
        for (int k = 0; k < 4; ++k) bv[k] = bias[f0 + lane + 32 * k];
    }
    float4 xq = make_float4(0.f, 0.f, 0.f, 0.f);
    if (tid < 256)                            // x tile: 8 rows x 32 quads
        xq = ((const float4*)(data + (size_t)(b0 + w) * F_NUM + f0))[lane];

    // ---- stage x tile ----
    if (tid < 256) xs4[w][lane] = xq;
    __syncthreads();

    // ---- main loop: v[b*4+c] accumulates s[w*4+c] for batch row b ----
    float v[32];
    #pragma unroll
    for (int i = 0; i < 32; ++i) v[i] = 0.f;

    {
        float4 xr[BPB];
        #pragma unroll
        for (int b = 0; b < BPB; ++b)
            xr[b] = xs4[b][fs * 2 + fh];      // LDS.128 broadcast
        #pragma unroll
        for (int jj = 0; jj < 4; ++jj) {
            const float4 vv = ev[jj];
            #pragma unroll
            for (int b = 0; b < BPB; ++b) {
                const float x = (jj == 0) ? xr[b].x :
                                (jj == 1) ? xr[b].y :
                                (jj == 2) ? xr[b].z : xr[b].w;
                v[b * 4 + 0] = fmaf(x, vv.x, v[b * 4 + 0]);
                v[b * 4 + 1] = fmaf(x, vv.y, v[b * 4 + 1]);
                v[b * 4 + 2] = fmaf(x, vv.z, v[b * 4 + 2]);
                v[b * 4 + 3] = fmaf(x, vv.w, v[b * 4 + 3]);
            }
        }
    }

    // ---- linear term: warps 0..7, warp w = batch row w ----
    if (w < BPB) {
        const float* xsf = (const float*)xs4; // [b][f], stride 128
        float l = 0.f;
        #pragma unroll
        for (int k = 0; k < 4; ++k)
            l = fmaf(xsf[w * FPB + lane + 32 * k], bv[k], l);
        #pragma unroll
        for (int off = 16; off >= 1; off >>= 1)
            l += __shfl_down_sync(0xffffffffu, l, off);
        if (lane == 0) atomicAdd(&g_lin[b0 + w], l);  // relaxed RED.ADD
    }

    // ---- 5-round reduce-scatter over (fh, fs): live set halves per round.
    // After round k, lane's window is pinned by its lane bits; the final
    // single value on lane l is the full sum of v[l] over all 32 lanes.
    #pragma unroll
    for (int off = 16, n = 16; off >= 1; off >>= 1, n >>= 1) {
        const bool up = (lane & off) != 0;
        #pragma unroll
        for (int i = 0; i < 16; ++i) {        // only i < n is live
            if (i < n) {
                const float s = up ? v[i + n] : v[i];
                v[i] = s + __shfl_xor_sync(0xffffffffu, s, off);
            }
        }
    }
    // lane l holds s-partial for batch row l>>2, component w*4 + (l&3)
    atomicAdd(&g_s[b0 + (lane >> 2)][w * 4 + (lane & 3)], v[0]);

    // ---- per-group acq_rel ticket (release our REDs / acquire others') ----
    __syncthreads();
    if (tid == 0) {
        unsigned int old;
        asm volatile("atom.acq_rel.gpu.global.add.u32 %0, [%1], 1;"
                     : "=r"(old) : "l"(&g_counter[bg * 32]) : "memory");
        s_ticket = old;
    }
    __syncthreads();
    if (s_ticket != (unsigned)(FGC - 1)) return;

    // ---- group finisher: 8 rows of THIS batch group only (2KB readback) ----
    if (w < BPB) {
        const int b = b0 + w;                 // warp w -> batch row b0+w
        const float lin_b = __ldcg(&g_lin[b]);
        const float gb    = __ldcg(&gbias[0]);
        const float2 sv   = __ldcg(((const float2*)g_s[b]) + lane);
        float ss = fmaf(sv.x, sv.x, sv.y * sv.y);
        #pragma unroll
        for (int off = 16; off >= 1; off >>= 1)
            ss += __shfl_down_sync(0xffffffffu, ss, off);
        if (lane == 0) {
            const float z = gb + lin_b + ss;
            out[b] = 1.0f / (1.0f + __expf(-z));
            g_lin[b] = 0.f;                   // reset for next replay
        }
        if (lane < 16)                        // reset s slice (16 float4)
            ((float4*)g_s[b])[lane] = make_float4(0.f, 0.f, 0.f, 0.f);
        if (lane == 0 && w == 0) g_counter[bg * 32] = 0u;
    }
}

extern "C" void kernel_launch(void* const* d_in, const int* in_sizes, int n_in,
                              void* d_out, int out_size) {
    const float* data  = (const float*)d_in[0];   // (64, 2048)
    const float* embed = (const float*)d_in[1];   // (2048, 64)
    const float* bias  = (const float*)d_in[2];   // (2048, 1)
    const float* gb    = (const float*)d_in[3];   // (1, 1)
    float* out = (float*)d_out;                   // (64,)
    (void)in_sizes; (void)n_in; (void)out_size;

    KTM_22110491640579_kernel<<<FGC * BGC, THREADS>>>(data, embed, bias, gb, out);
}

// round 13
// speedup vs baseline: 1.0355x; 1.0355x over previous
#include <cuda_runtime.h>
#include <cuda_bf16.h>
#include <math.h>

// pred[b] = sigmoid(gb + data[b,:].bias + || data[b,:] @ embed ||^2)
//   (the (B,F,F) Gram double-sum collapses to the squared norm of s = x @ V)
//
// Grid = 128 blocks (fg 0..15 x bg 0..7), 256 threads, one wave.
// Block (fg, bg): 8 batch rows x 128 features x all 64 dims.
//   - NO smem staging, NO front barrier: x quads read straight from gmem
//     (warp-shared addresses hit L1 after first touch); front-batched with
//     the 8 embed LDG.128 (MLP ~18) so L2 latency is fully overlapped
//   - linear term computed from the warp's own registers (row-w x quad .
//     bias quad), independent of all other warps
//   - reduce-scatter butterfly over the 16 feature slices (live set halves
//     per round); 2 full-warp spread REDG.ADD emit
//   - hierarchical finish: one acq_rel ticket per batch group (8 counters on
//     distinct 128B lines); the 16th block of a group finishes its 8 rows
//     (2KB readback) and resets its slice + counter (replay-deterministic).

#define F_NUM   2048
#define D_DIM   64
#define BATCH   64
#define THREADS 256
#define BGC     8          // batch groups (8 rows each)
#define FGC     16         // feature groups per batch group
#define FPB     128        // features per block
#define BPB     8          // batch rows per block

__device__ float        g_s[BATCH][D_DIM];   // zero-init; re-zeroed by finishers
__device__ float        g_lin[BATCH];
__device__ unsigned int g_counter[BGC * 32]; // one counter per 128B line

__global__ __launch_bounds__(THREADS, 1)
void KTM_22110491640579_kernel(const float* __restrict__ data,
                               const float* __restrict__ embed,
                               const float* __restrict__ bias,
                               const float* __restrict__ gbias,
                               float* __restrict__ out) {
    __shared__ unsigned int s_ticket;

    const int tid  = threadIdx.x;
    const int fg   = blockIdx.x & (FGC - 1);  // 0..15
    const int bg   = blockIdx.x >> 4;         // 0..7
    const int f0   = fg * FPB;
    const int b0   = bg * BPB;
    const int w    = tid >> 5;                // warp 0..7
    const int lane = tid & 31;

    const int dq = (w << 1) | (lane >> 4);    // 0..15: quad of the s vector
    const int fs = lane & 15;                 // 0..15: 8-feature slice
    const float4* V4 = ((const float4*)embed) + ((size_t)(f0 + fs * 8) * 16 + dq);
    const float4* X4 = (const float4*)(data + (size_t)b0 * F_NUM + f0);
    // row stride in float4 units
    #define XROW (F_NUM / 4)

    // ---- front-batch: 8 embed quads + first 8 x quads + lin operands ----
    float4 ev[8];
    #pragma unroll
    for (int j = 0; j < 8; ++j) ev[j] = V4[(size_t)j * 16];
    float4 xr[BPB];
    #pragma unroll
    for (int b = 0; b < BPB; ++b) xr[b] = X4[(size_t)b * XROW + fs * 2];
    const float4 xq  = X4[(size_t)w * XROW + lane];        // row w, quad lane
    const float4 bq  = ((const float4*)bias)[f0 / 4 + lane];

    // ---- main loop: v[b*4+c] accumulates s[dq*4+c] for batch row b ----
    float v[32];
    #pragma unroll
    for (int i = 0; i < 32; ++i) v[i] = 0.f;

    #pragma unroll
    for (int jq = 0; jq < 2; ++jq) {          // two float4 groups of 4 features
        if (jq == 1) {                        // second x batch (L1-hot)
            #pragma unroll
            for (int b = 0; b < BPB; ++b) xr[b] = X4[(size_t)b * XROW + fs * 2 + 1];
        }
        #pragma unroll
        for (int jj = 0; jj < 4; ++jj) {
            const float4 vv = ev[jq * 4 + jj];
            #pragma unroll
            for (int b = 0; b < BPB; ++b) {
                const float x = (jj == 0) ? xr[b].x :
                                (jj == 1) ? xr[b].y :
                                (jj == 2) ? xr[b].z : xr[b].w;
                v[b * 4 + 0] = fmaf(x, vv.x, v[b * 4 + 0]);
                v[b * 4 + 1] = fmaf(x, vv.y, v[b * 4 + 1]);
                v[b * 4 + 2] = fmaf(x, vv.z, v[b * 4 + 2]);
                v[b * 4 + 3] = fmaf(x, vv.w, v[b * 4 + 3]);
            }
        }
    }

    // ---- linear term: warp w = batch row w, all from registers ----
    {
        float l = xq.x * bq.x + xq.y * bq.y + xq.z * bq.z + xq.w * bq.w;
        #pragma unroll
        for (int off = 16; off >= 1; off >>= 1)
            l += __shfl_down_sync(0xffffffffu, l, off);
        if (lane == 0) atomicAdd(&g_lin[b0 + w], l);  // relaxed RED.ADD
    }

    // ---- reduce-scatter over fs (lane bits 0..3): live set halves/round ----
    // After the 4 rounds, lane fs holds batch row fs>>1, components
    // (fs&1)*2 + {0,1} of its dq quad.
    #pragma unroll
    for (int off = 8, n = 16; off >= 1; off >>= 1, n >>= 1) {
        const bool up = (fs & off) != 0;
        #pragma unroll
        for (int i = 0; i < 16; ++i) {        // only i < n is live
            if (i < n) {
                const float s = up ? v[i + n] : v[i];
                v[i] = s + __shfl_xor_sync(0xffffffffu, s, off);
            }
        }
    }
    {
        float* dst = &g_s[b0 + (fs >> 1)][dq * 4 + (fs & 1) * 2];
        atomicAdd(dst + 0, v[0]);             // full-warp spread REDG.ADD
        atomicAdd(dst + 1, v[1]);
    }

    // ---- per-group acq_rel ticket (release our REDs / acquire others') ----
    __syncthreads();                          // all warps' REDs issued
    if (tid == 0) {
        unsigned int old;
        asm volatile("atom.acq_rel.gpu.global.add.u32 %0, [%1], 1;"
                     : "=r"(old) : "l"(&g_counter[bg * 32]) : "memory");
        s_ticket = old;
    }
    __syncthreads();
    if (s_ticket != (unsigned)(FGC - 1)) return;

    // ---- group finisher: 8 rows of THIS batch group only (2KB readback) ----
    {
        const int b = b0 + w;                 // warp w -> batch row b0+w
        const float lin_b = __ldcg(&g_lin[b]);
        const float gb    = __ldcg(&gbias[0]);
        const float2 sv   = __ldcg(((const float2*)g_s[b]) + lane);
        float ss = fmaf(sv.x, sv.x, sv.y * sv.y);
        #pragma unroll
        for (int off = 16; off >= 1; off >>= 1)
            ss += __shfl_down_sync(0xffffffffu, ss, off);
        if (lane == 0) {
            const float z = gb + lin_b + ss;
            out[b] = 1.0f / (1.0f + __expf(-z));
            g_lin[b] = 0.f;                   // reset for next replay
        }
        if (lane < 16)                        // reset s slice (16 float4)
            ((float4*)g_s[b])[lane] = make_float4(0.f, 0.f, 0.f, 0.f);
        if (tid == 0) g_counter[bg * 32] = 0u;
    }
    #undef XROW
}

extern "C" void kernel_launch(void* const* d_in, const int* in_sizes, int n_in,
                              void* d_out, int out_size) {
    const float* data  = (const float*)d_in[0];   // (64, 2048)
    const float* embed = (const float*)d_in[1];   // (2048, 64)
    const float* bias  = (const float*)d_in[2];   // (2048, 1)
    const float* gb    = (const float*)d_in[3];   // (1, 1)
    float* out = (float*)d_out;                   // (64,)
    (void)in_sizes; (void)n_in; (void)out_size;

    KTM_22110491640579_kernel<<<FGC * BGC, THREADS>>>(data, embed, bias, gb, out);
}

// round 15
// speedup vs baseline: 1.1845x; 1.1439x over previous
#include <cuda_runtime.h>
#include <cuda_bf16.h>
#include <math.h>

// pred[b] = sigmoid(gb + data[b,:].bias + || data[b,:] @ embed ||^2)
//   (the (B,F,F) Gram double-sum collapses to the squared norm of s = x @ V)
//
// Grid = 128 blocks (fg 0..15 x bg 0..7), 256 threads, one wave.
// Block (fg, bg): 8 batch rows x 128 features x all 64 dims.
//   - x tile in smem; ALL global loads front-batched (8 embed LDG.128 +
//     4 bias + 1 x) so L2 latency overlaps the x STS/BAR drain
//   - reduce-scatter butterfly over the 16 feature slices (live set halves
//     per round); 2 full-warp spread REDG.ADD emit
//   - WARP-GRANULAR finish: each warp arrives independently on its batch
//     group's acq_rel counter (target 16 blocks x 8 warps = 128) and returns;
//     no trailing block barriers. The 128th warp finishes its group's 8 rows
//     (4 lanes/row, 2-SHFL reduce) and resets slice + counter
//     (replay-deterministic).

#define F_NUM   2048
#define D_DIM   64
#define BATCH   64
#define THREADS 256
#define BGC     8          // batch groups (8 rows each)
#define FGC     16         // feature groups per batch group
#define FPB     128        // features per block
#define BPB     8          // batch rows per block
#define WARRIVALS (FGC * 8)  // warp arrivals per group counter

__device__ float        g_s[BATCH][D_DIM];   // zero-init; re-zeroed by finishers
__device__ float        g_lin[BATCH];
__device__ unsigned int g_counter[BGC * 32]; // one counter per 128B line

__global__ __launch_bounds__(THREADS, 1)
void KTM_22110491640579_kernel(const float* __restrict__ data,
                               const float* __restrict__ embed,
                               const float* __restrict__ bias,
                               const float* __restrict__ gbias,
                               float* __restrict__ out) {
    __shared__ float4 xs4[BPB][FPB / 4];      // 4 KB x tile [8][32 quads]

    const int tid  = threadIdx.x;
    const int fg   = blockIdx.x & (FGC - 1);  // 0..15
    const int bg   = blockIdx.x >> 4;         // 0..7
    const int f0   = fg * FPB;
    const int b0   = bg * BPB;
    const int w    = tid >> 5;                // warp 0..7
    const int lane = tid & 31;

    const int dq = (w << 1) | (lane >> 4);    // 0..15: quad of the s vector
    const int fs = lane & 15;                 // 0..15: 8-feature slice
    const float4* V4 = ((const float4*)embed) + ((size_t)(f0 + fs * 8) * 16 + dq);

    // ---- front-batch ALL global loads (independent addresses, MLP ~13) ----
    float4 ev[8];                             // embed quads for this thread
    #pragma unroll
    for (int j = 0; j < 8; ++j) ev[j] = V4[(size_t)j * 16];
    float bv[4];                              // bias slice for the linear term
    #pragma unroll
    for (int k = 0; k < 4; ++k) bv[k] = bias[f0 + lane + 32 * k];
    const float4 xq =                         // this thread's x quad
        ((const float4*)(data + (size_t)(b0 + w) * F_NUM + f0))[lane];

    // ---- stage x tile: 8 rows x 128 floats ----
    xs4[w][lane] = xq;
    __syncthreads();

    // ---- main loop: v[b*4+c] accumulates s[dq*4+c] for batch row b ----
    float v[32];
    #pragma unroll
    for (int i = 0; i < 32; ++i) v[i] = 0.f;

    #pragma unroll
    for (int jq = 0; jq < 2; ++jq) {          // two float4 groups of 4 features
        float4 xr[BPB];
        #pragma unroll
        for (int b = 0; b < BPB; ++b)
            xr[b] = xs4[b][fs * 2 + jq];      // LDS.128, half-warp broadcast
        #pragma unroll
        for (int jj = 0; jj < 4; ++jj) {
            const float4 vv = ev[jq * 4 + jj];
            #pragma unroll
            for (int b = 0; b < BPB; ++b) {
                const float x = (jj == 0) ? xr[b].x :
                                (jj == 1) ? xr[b].y :
                                (jj == 2) ? xr[b].z : xr[b].w;
                v[b * 4 + 0] = fmaf(x, vv.x, v[b * 4 + 0]);
                v[b * 4 + 1] = fmaf(x, vv.y, v[b * 4 + 1]);
                v[b * 4 + 2] = fmaf(x, vv.z, v[b * 4 + 2]);
                v[b * 4 + 3] = fmaf(x, vv.w, v[b * 4 + 3]);
            }
        }
    }

    // ---- linear term: warp w handles batch row w, full-warp shfl reduce ----
    {
        const float* xsf = (const float*)xs4; // [b][f], stride 128
        float l = 0.f;
        #pragma unroll
        for (int k = 0; k < 4; ++k)
            l = fmaf(xsf[w * FPB + lane + 32 * k], bv[k], l);
        #pragma unroll
        for (int off = 16; off >= 1; off >>= 1)
            l += __shfl_down_sync(0xffffffffu, l, off);
        if (lane == 0) atomicAdd(&g_lin[b0 + w], l);  // relaxed RED.ADD
    }

    // ---- reduce-scatter over fs (lane bits 0..3): live set halves/round ----
    // After the 4 rounds, lane fs holds batch row fs>>1, components
    // (fs&1)*2 + {0,1} of its dq quad.
    #pragma unroll
    for (int off = 8, n = 16; off >= 1; off >>= 1, n >>= 1) {
        const bool up = (fs & off) != 0;
        #pragma unroll
        for (int i = 0; i < 16; ++i) {        // only i < n is live
            if (i < n) {
                const float s = up ? v[i + n] : v[i];
                v[i] = s + __shfl_xor_sync(0xffffffffu, s, off);
            }
        }
    }
    {
        float* dst = &g_s[b0 + (fs >> 1)][dq * 4 + (fs & 1) * 2];
        atomicAdd(dst + 0, v[0]);             // full-warp spread REDG.ADD
        atomicAdd(dst + 1, v[1]);
    }

    // ---- warp-granular acq_rel ticket: no trailing block barriers ----
    __syncwarp();                             // order this warp's REDs
    unsigned int old = 0u;
    if (lane == 0) {
        asm volatile("atom.acq_rel.gpu.global.add.u32 %0, [%1], 1;"
                     : "=r"(old) : "l"(&g_counter[bg * 32]) : "memory");
    }
    old = __shfl_sync(0xffffffffu, old, 0);
    if (old != (unsigned)(WARRIVALS - 1)) return;
    __syncwarp();                             // publish lane0's acquire

    // ---- finisher WARP: 8 rows, 4 lanes per row (16 dims each) ----
    {
        const int r = lane >> 2;              // 0..7 -> batch row b0+r
        const int p = lane & 3;               // 0..3 -> dims p*16..p*16+15
        const int b = b0 + r;
        const float lin_b = __ldcg(&g_lin[b]);
        const float gb    = __ldcg(&gbias[0]);
        const float4* sp  = ((const float4*)g_s[b]) + p * 4;
        float ss = 0.f;
        #pragma unroll
        for (int k = 0; k < 4; ++k) {
            const float4 q = __ldcg(sp + k);
            ss = fmaf(q.x, q.x, ss);
            ss = fmaf(q.y, q.y, ss);
            ss = fmaf(q.z, q.z, ss);
            ss = fmaf(q.w, q.w, ss);
        }
        ss += __shfl_xor_sync(0xffffffffu, ss, 1);
        ss += __shfl_xor_sync(0xffffffffu, ss, 2);
        if (p == 0) {
            const float z = gb + lin_b + ss;
            out[b] = 1.0f / (1.0f + __expf(-z));
            g_lin[b] = 0.f;                   // reset for next replay
        }
        float4* rp = ((float4*)g_s[b]) + p * 4;
        const float4 z4 = make_float4(0.f, 0.f, 0.f, 0.f);
        #pragma unroll
        for (int k = 0; k < 4; ++k) rp[k] = z4;  // reset s slice
        if (lane == 0) g_counter[bg * 32] = 0u;
    }
}

extern "C" void kernel_launch(void* const* d_in, const int* in_sizes, int n_in,
                              void* d_out, int out_size) {
    const float* data  = (const float*)d_in[0];   // (64, 2048)
    const float* embed = (const float*)d_in[1];   // (2048, 64)
    const float* bias  = (const float*)d_in[2];   // (2048, 1)
    const float* gb    = (const float*)d_in[3];   // (1, 1)
    float* out = (float*)d_out;                   // (64,)
    (void)in_sizes; (void)n_in; (void)out_size;

    KTM_22110491640579_kernel<<<FGC * BGC, THREADS>>>(data, embed, bias, gb, out);
}